// round 2
// baseline (speedup 1.0000x reference)
#include <cuda_runtime.h>
#include <cuda_fp16.h>
#include <cstdint>

#define M_TOTAL 4096
#define N_TOTAL 4096
#define K_TOTAL 4096

// Persistent scratch: fp16 activations and dequantized weights (K-major [rows, K])
__device__ __align__(1024) __half g_X[(size_t)M_TOTAL * K_TOTAL];
__device__ __align__(1024) __half g_W[(size_t)N_TOTAL * K_TOTAL];

// ---------------------------------------------------------------------------
// x: f32 -> f16   (each thread converts 8 floats)
// ---------------------------------------------------------------------------
__global__ void __launch_bounds__(256) k_convert_x(const float* __restrict__ x) {
    size_t i = (size_t)blockIdx.x * blockDim.x + threadIdx.x;
    const float4* xf = reinterpret_cast<const float4*>(x);
    float4 a = xf[2 * i];
    float4 b = xf[2 * i + 1];
    __half2 h0 = __floats2half2_rn(a.x, a.y);
    __half2 h1 = __floats2half2_rn(a.z, a.w);
    __half2 h2 = __floats2half2_rn(b.x, b.y);
    __half2 h3 = __floats2half2_rn(b.z, b.w);
    uint4 u;
    u.x = *reinterpret_cast<uint32_t*>(&h0);
    u.y = *reinterpret_cast<uint32_t*>(&h1);
    u.z = *reinterpret_cast<uint32_t*>(&h2);
    u.w = *reinterpret_cast<uint32_t*>(&h3);
    reinterpret_cast<uint4*>(g_X)[i] = u;
}

// ---------------------------------------------------------------------------
// Q4_K dequant: one thread per packed byte -> 2 fp16 weights
// w = q*(sc*d/945) + (mn*d/63 + dmin);  e=2i -> low nibble, e=2i+1 -> high
// ---------------------------------------------------------------------------
__global__ void __launch_bounds__(256) k_dequant(const int* __restrict__ packed,
                                                 const float* __restrict__ d,
                                                 const float* __restrict__ dmin,
                                                 const int* __restrict__ scales,
                                                 const int* __restrict__ mins) {
    int i = blockIdx.x * 256 + threadIdx.x;       // byte index [0, 8388608)
    int s = i >> 7;                               // superblock
    int idx8 = (s << 3) | ((i >> 4) & 7);         // sub-block index
    float dd = d[s];
    float sc = (float)scales[idx8] * dd * (1.0f / 945.0f);
    float mn = (float)mins[idx8] * dd * (1.0f / 63.0f) + dmin[s];
    int v = packed[i];
    float w0 = (float)(v & 15) * sc + mn;
    float w1 = (float)((v >> 4) & 15) * sc + mn;
    reinterpret_cast<__half2*>(g_W)[i] = __floats2half2_rn(w0, w1);
}

// ---------------------------------------------------------------------------
// GEMM via mma.sync.m16n8k16 (base-ISA tensor path; tcgen05 unavailable:
// harness PTX target is compute_103 without the 'a' suffix).
// Tile: BM=128 x BN=256 x BK=64, 8 warps, warp tile 64x64, 3-stage cp.async.
// ---------------------------------------------------------------------------
#define BM 128
#define BN 256
#define BK 64                            // 64 halves = 128 B per row (SW128)
#define NS 3
#define NKT (K_TOTAL / BK)               // 64
#define A_BYTES (BM * 128)               // 16384
#define B_BYTES (BN * 128)               // 32768
#define STAGE_BYTES (A_BYTES + B_BYTES)  // 49152
#define SMEM_TOTAL (NS * STAGE_BYTES)    // 147456

__device__ __forceinline__ uint32_t s2u(const void* p) {
    uint32_t a;
    asm("{ .reg .u64 t; cvta.to.shared.u64 t, %1; cvt.u32.u64 %0, t; }"
        : "=r"(a) : "l"(p));
    return a;
}

__device__ __forceinline__ uint32_t swz(uint32_t o) { return o ^ ((o >> 3) & 0x70); }

__device__ __forceinline__ void cp16(uint32_t dst, const void* src) {
    asm volatile("cp.async.cg.shared.global [%0], [%1], 16;" :: "r"(dst), "l"(src));
}

__device__ __forceinline__ void ldmx4(uint32_t* r, uint32_t addr) {
    asm volatile("ldmatrix.sync.aligned.m8n8.x4.shared.b16 {%0,%1,%2,%3}, [%4];"
                 : "=r"(r[0]), "=r"(r[1]), "=r"(r[2]), "=r"(r[3]) : "r"(addr));
}

__device__ __forceinline__ void mma16816(float* c, const uint32_t* a,
                                         uint32_t b0, uint32_t b1) {
    asm volatile(
        "mma.sync.aligned.m16n8k16.row.col.f32.f16.f16.f32 "
        "{%0,%1,%2,%3}, {%4,%5,%6,%7}, {%8,%9}, {%0,%1,%2,%3};"
        : "+f"(c[0]), "+f"(c[1]), "+f"(c[2]), "+f"(c[3])
        : "r"(a[0]), "r"(a[1]), "r"(a[2]), "r"(a[3]), "r"(b0), "r"(b1));
}

// One stage's loads: A 128x64 halves + B 256x64 halves, SW128 swizzled.
// 16B chunks: A 1024, B 2048; 256 threads.
__device__ __forceinline__ void issue_loads(uint32_t sbase, int kt, int tid,
                                            const __half* Ag, const __half* Bg) {
    const __half* Ak = Ag + kt * BK;
    const __half* Bk = Bg + kt * BK;
    uint32_t bbase = sbase + A_BYTES;
#pragma unroll
    for (int q = 0; q < 4; q++) {
        int i = tid + q * 256;
        int row = i >> 3, c = i & 7;
        cp16(sbase + swz((uint32_t)(row * 128 + c * 16)),
             Ak + (size_t)row * K_TOTAL + c * 8);
    }
#pragma unroll
    for (int q = 0; q < 8; q++) {
        int i = tid + q * 256;
        int row = i >> 3, c = i & 7;
        cp16(bbase + swz((uint32_t)(row * 128 + c * 16)),
             Bk + (size_t)row * K_TOTAL + c * 8);
    }
}

__global__ void __launch_bounds__(256, 1) k_gemm(float* __restrict__ out) {
    extern __shared__ char smem[];
    uint32_t sb = s2u(smem);
    int tid = threadIdx.x;
    int lane = tid & 31;
    int wid = tid >> 5;
    int wm = wid >> 2;        // 0..1  (m block of 64)
    int wn = wid & 3;         // 0..3  (n block of 64)
    int m0 = blockIdx.y * BM;
    int n0 = blockIdx.x * BN;

    const __half* Ag = g_X + (size_t)m0 * K_TOTAL;
    const __half* Bg = g_W + (size_t)n0 * K_TOTAL;

    float c[4][8][4];
#pragma unroll
    for (int mi = 0; mi < 4; mi++)
#pragma unroll
        for (int ni = 0; ni < 8; ni++)
#pragma unroll
            for (int j = 0; j < 4; j++) c[mi][ni][j] = 0.0f;

    // ldmatrix per-lane address bases (unswizzled byte offsets within tile)
    // A (m16k16, x4): row = base + (lane&15), +16B for lanes 16..31
    // B (n16k16, x4): row = base + (lane&7) + 8*(lane>=16), +16B for lane&8
    int ar = lane & 15;
    int ak = (lane >> 4) << 4;
    int br = (lane & 7) | ((lane & 16) >> 1);
    int bk = (lane & 8) << 1;
    uint32_t am[4], bnb[4];
#pragma unroll
    for (int mi = 0; mi < 4; mi++)
        am[mi] = (uint32_t)((wm * 64 + mi * 16 + ar) * 128 + ak);
#pragma unroll
    for (int nb = 0; nb < 4; nb++)
        bnb[nb] = (uint32_t)((wn * 64 + nb * 16 + br) * 128 + bk);

    // Prologue: fill all stages
#pragma unroll
    for (int p = 0; p < NS; p++) {
        issue_loads(sb + p * STAGE_BYTES, p, tid, Ag, Bg);
        asm volatile("cp.async.commit_group;" ::: "memory");
    }

    int s = 0;
    for (int kt = 0; kt < NKT; kt++) {
        if (kt < NKT - 2)      asm volatile("cp.async.wait_group 2;" ::: "memory");
        else if (kt == NKT - 2) asm volatile("cp.async.wait_group 1;" ::: "memory");
        else                   asm volatile("cp.async.wait_group 0;" ::: "memory");
        __syncthreads();

        uint32_t ab = sb + (uint32_t)s * STAGE_BYTES;
        uint32_t bb = ab + A_BYTES;
#pragma unroll
        for (int ks = 0; ks < 4; ks++) {
            uint32_t a[4][4], b[4][4];
#pragma unroll
            for (int mi = 0; mi < 4; mi++)
                ldmx4(a[mi], ab + swz(am[mi] + ks * 32));
#pragma unroll
            for (int nb = 0; nb < 4; nb++)
                ldmx4(b[nb], bb + swz(bnb[nb] + ks * 32));
#pragma unroll
            for (int mi = 0; mi < 4; mi++)
#pragma unroll
                for (int nb = 0; nb < 4; nb++) {
                    mma16816(c[mi][2 * nb],     a[mi], b[nb][0], b[nb][1]);
                    mma16816(c[mi][2 * nb + 1], a[mi], b[nb][2], b[nb][3]);
                }
        }
        __syncthreads();

        if (kt + NS < NKT) {
            issue_loads(sb + (uint32_t)s * STAGE_BYTES, kt + NS, tid, Ag, Bg);
            asm volatile("cp.async.commit_group;" ::: "memory");
        }
        if (++s == NS) s = 0;
    }

    // Epilogue: direct f32 stores. c fragment rows: lane/4 and lane/4+8,
    // cols: 2*(lane%4)+{0,1}.
    int rbase = m0 + wm * 64 + (lane >> 2);
    int cbase = n0 + wn * 64 + (lane & 3) * 2;
#pragma unroll
    for (int mi = 0; mi < 4; mi++) {
#pragma unroll
        for (int ni = 0; ni < 8; ni++) {
            float* p = out + (size_t)(rbase + mi * 16) * N_TOTAL + cbase + ni * 8;
            float2 v0 = make_float2(c[mi][ni][0], c[mi][ni][1]);
            float2 v1 = make_float2(c[mi][ni][2], c[mi][ni][3]);
            *reinterpret_cast<float2*>(p) = v0;
            *reinterpret_cast<float2*>(p + 8 * N_TOTAL) = v1;
        }
    }
}

// ---------------------------------------------------------------------------
extern "C" void kernel_launch(void* const* d_in, const int* in_sizes, int n_in,
                              void* d_out, int out_size) {
    const float* x      = (const float*)d_in[0];
    const int*   packed = (const int*)d_in[1];
    const float* d      = (const float*)d_in[2];
    const float* dmin   = (const float*)d_in[3];
    const int*   scales = (const int*)d_in[4];
    const int*   mins   = (const int*)d_in[5];
    float* out = (float*)d_out;

    (void)in_sizes; (void)n_in; (void)out_size;

    cudaFuncSetAttribute(k_gemm, cudaFuncAttributeMaxDynamicSharedMemorySize, SMEM_TOTAL);

    k_convert_x<<<(M_TOTAL * K_TOTAL / 8) / 256, 256>>>(x);
    k_dequant<<<(N_TOTAL * K_TOTAL / 2) / 256, 256>>>(packed, d, dmin, scales, mins);
    k_gemm<<<dim3(N_TOTAL / BN, M_TOTAL / BM), 256, SMEM_TOTAL>>>(out);
}

// round 3
// speedup vs baseline: 1.2006x; 1.2006x over previous
#include <cuda_runtime.h>
#include <cuda_fp16.h>
#include <cstdint>

#define M_TOTAL 4096
#define N_TOTAL 4096
#define K_TOTAL 4096

// Persistent scratch: fp16 activations and dequantized weights (K-major [rows, K])
__device__ __align__(1024) __half g_X[(size_t)M_TOTAL * K_TOTAL];
__device__ __align__(1024) __half g_W[(size_t)N_TOTAL * K_TOTAL];

// ---------------------------------------------------------------------------
// x: f32 -> f16   (each thread converts 8 floats)
// ---------------------------------------------------------------------------
__global__ void __launch_bounds__(256) k_convert_x(const float* __restrict__ x) {
    size_t i = (size_t)blockIdx.x * blockDim.x + threadIdx.x;
    const float4* xf = reinterpret_cast<const float4*>(x);
    float4 a = xf[2 * i];
    float4 b = xf[2 * i + 1];
    __half2 h0 = __floats2half2_rn(a.x, a.y);
    __half2 h1 = __floats2half2_rn(a.z, a.w);
    __half2 h2 = __floats2half2_rn(b.x, b.y);
    __half2 h3 = __floats2half2_rn(b.z, b.w);
    uint4 u;
    u.x = *reinterpret_cast<uint32_t*>(&h0);
    u.y = *reinterpret_cast<uint32_t*>(&h1);
    u.z = *reinterpret_cast<uint32_t*>(&h2);
    u.w = *reinterpret_cast<uint32_t*>(&h3);
    reinterpret_cast<uint4*>(g_X)[i] = u;
}

// ---------------------------------------------------------------------------
// Q4_K dequant: one thread per packed byte -> 2 fp16 weights
// w = q*(sc*d/945) + (mn*d/63 + dmin);  e=2i -> low nibble, e=2i+1 -> high
// ---------------------------------------------------------------------------
__global__ void __launch_bounds__(256) k_dequant(const int* __restrict__ packed,
                                                 const float* __restrict__ d,
                                                 const float* __restrict__ dmin,
                                                 const int* __restrict__ scales,
                                                 const int* __restrict__ mins) {
    int i = blockIdx.x * 256 + threadIdx.x;       // byte index [0, 8388608)
    int s = i >> 7;                               // superblock
    int idx8 = (s << 3) | ((i >> 4) & 7);         // sub-block index
    float dd = d[s];
    float sc = (float)scales[idx8] * dd * (1.0f / 945.0f);
    float mn = (float)mins[idx8] * dd * (1.0f / 63.0f) + dmin[s];
    int v = packed[i];
    float w0 = (float)(v & 15) * sc + mn;
    float w1 = (float)((v >> 4) & 15) * sc + mn;
    reinterpret_cast<__half2*>(g_W)[i] = __floats2half2_rn(w0, w1);
}

// ---------------------------------------------------------------------------
// GEMM via mma.sync.m16n8k16 (base-ISA path; tcgen05 unavailable on the
// harness's compute_103 PTX target).
// Tile: BM=128 x BN=256 x BK=64, 8 warps, warp tile 64x64.
// CUTLASS-style multistage: NS=4, one syncthreads per k-tile, register
// double-buffered fragments, refill issued at head of iteration.
// ---------------------------------------------------------------------------
#define BM 128
#define BN 256
#define BK 64                            // 64 halves = 128 B per row (SW128)
#define NS 4
#define NKT (K_TOTAL / BK)               // 64
#define A_BYTES (BM * 128)               // 16384
#define B_BYTES (BN * 128)               // 32768
#define STAGE_BYTES (A_BYTES + B_BYTES)  // 49152
#define SMEM_TOTAL (NS * STAGE_BYTES)    // 196608

__device__ __forceinline__ uint32_t s2u(const void* p) {
    uint32_t a;
    asm("{ .reg .u64 t; cvta.to.shared.u64 t, %1; cvt.u32.u64 %0, t; }"
        : "=r"(a) : "l"(p));
    return a;
}

__device__ __forceinline__ uint32_t swz(uint32_t o) { return o ^ ((o >> 3) & 0x70); }

__device__ __forceinline__ void cp16(uint32_t dst, const void* src) {
    asm volatile("cp.async.cg.shared.global [%0], [%1], 16;" :: "r"(dst), "l"(src));
}

__device__ __forceinline__ void ldmx4(uint32_t* r, uint32_t addr) {
    asm volatile("ldmatrix.sync.aligned.m8n8.x4.shared.b16 {%0,%1,%2,%3}, [%4];"
                 : "=r"(r[0]), "=r"(r[1]), "=r"(r[2]), "=r"(r[3]) : "r"(addr));
}

__device__ __forceinline__ void mma16816(float* c, const uint32_t* a,
                                         uint32_t b0, uint32_t b1) {
    asm volatile(
        "mma.sync.aligned.m16n8k16.row.col.f32.f16.f16.f32 "
        "{%0,%1,%2,%3}, {%4,%5,%6,%7}, {%8,%9}, {%0,%1,%2,%3};"
        : "+f"(c[0]), "+f"(c[1]), "+f"(c[2]), "+f"(c[3])
        : "r"(a[0]), "r"(a[1]), "r"(a[2]), "r"(a[3]), "r"(b0), "r"(b1));
}

// One stage's loads: A 128x64 halves + B 256x64 halves, SW128 swizzled.
__device__ __forceinline__ void issue_loads(uint32_t sbase, int kt, int tid,
                                            const __half* Ag, const __half* Bg) {
    const __half* Ak = Ag + kt * BK;
    const __half* Bk = Bg + kt * BK;
    uint32_t bbase = sbase + A_BYTES;
#pragma unroll
    for (int q = 0; q < 4; q++) {
        int i = tid + q * 256;
        int row = i >> 3, c = i & 7;
        cp16(sbase + swz((uint32_t)(row * 128 + c * 16)),
             Ak + (size_t)row * K_TOTAL + c * 8);
    }
#pragma unroll
    for (int q = 0; q < 8; q++) {
        int i = tid + q * 256;
        int row = i >> 3, c = i & 7;
        cp16(bbase + swz((uint32_t)(row * 128 + c * 16)),
             Bk + (size_t)row * K_TOTAL + c * 8);
    }
}

__global__ void __launch_bounds__(256, 1) k_gemm(float* __restrict__ out) {
    extern __shared__ char smem[];
    uint32_t sb = s2u(smem);
    int tid = threadIdx.x;
    int lane = tid & 31;
    int wid = tid >> 5;
    int wm = wid >> 2;        // 0..1  (m block of 64)
    int wn = wid & 3;         // 0..3  (n block of 64)
    int m0 = blockIdx.y * BM;
    int n0 = blockIdx.x * BN;

    const __half* Ag = g_X + (size_t)m0 * K_TOTAL;
    const __half* Bg = g_W + (size_t)n0 * K_TOTAL;

    float c[4][8][4];
#pragma unroll
    for (int mi = 0; mi < 4; mi++)
#pragma unroll
        for (int ni = 0; ni < 8; ni++)
#pragma unroll
            for (int j = 0; j < 4; j++) c[mi][ni][j] = 0.0f;

    // ldmatrix per-lane base byte offsets (unswizzled, within tile)
    int ar = lane & 15;
    int ak = (lane >> 4) << 4;
    int br = (lane & 7) | ((lane & 16) >> 1);
    int bk = (lane & 8) << 1;
    uint32_t am[4], bnb[4];
#pragma unroll
    for (int mi = 0; mi < 4; mi++)
        am[mi] = (uint32_t)((wm * 64 + mi * 16 + ar) * 128 + ak);
#pragma unroll
    for (int nb = 0; nb < 4; nb++)
        bnb[nb] = (uint32_t)((wn * 64 + nb * 16 + br) * 128 + bk);

    // Prologue: fill stages 0..NS-2
#pragma unroll
    for (int p = 0; p < NS - 1; p++) {
        issue_loads(sb + p * STAGE_BYTES, p, tid, Ag, Bg);
        asm volatile("cp.async.commit_group;" ::: "memory");
    }
    asm volatile("cp.async.wait_group %0;" :: "n"(NS - 2) : "memory");
    __syncthreads();

    uint32_t afr[2][4][4], bfr[2][4][4];
    int s_read = 0, s_write = NS - 1;
    uint32_t ab = sb;             // stage 0 A base
    uint32_t bb = sb + A_BYTES;   // stage 0 B base

    // Preload fragments for kt=0, ks=0
#pragma unroll
    for (int mi = 0; mi < 4; mi++) ldmx4(afr[0][mi], ab + swz(am[mi]));
#pragma unroll
    for (int nb = 0; nb < 4; nb++) ldmx4(bfr[0][nb], bb + swz(bnb[nb]));

    int cur = 0;
    for (int kt = 0; kt < NKT; kt++) {
        // Refill freed stage for tile kt+NS-1 (overlaps with this tile's math)
        if (kt + NS - 1 < NKT)
            issue_loads(sb + (uint32_t)s_write * STAGE_BYTES, kt + NS - 1, tid, Ag, Bg);
        asm volatile("cp.async.commit_group;" ::: "memory");

#pragma unroll
        for (int ks = 0; ks < 4; ks++) {
            int nxt = cur ^ 1;
            if (ks < 3) {
#pragma unroll
                for (int mi = 0; mi < 4; mi++)
                    ldmx4(afr[nxt][mi], ab + swz(am[mi] + (ks + 1) * 32));
#pragma unroll
                for (int nb = 0; nb < 4; nb++)
                    ldmx4(bfr[nxt][nb], bb + swz(bnb[nb] + (ks + 1) * 32));
            } else {
                // Stage boundary: next stage's loads are complete after this wait
                asm volatile("cp.async.wait_group %0;" :: "n"(NS - 2) : "memory");
                __syncthreads();
                s_read = (s_read + 1) & (NS - 1);
                s_write = (s_write + 1) & (NS - 1);
                ab = sb + (uint32_t)s_read * STAGE_BYTES;
                bb = ab + A_BYTES;
                if (kt < NKT - 1) {
#pragma unroll
                    for (int mi = 0; mi < 4; mi++)
                        ldmx4(afr[nxt][mi], ab + swz(am[mi]));
#pragma unroll
                    for (int nb = 0; nb < 4; nb++)
                        ldmx4(bfr[nxt][nb], bb + swz(bnb[nb]));
                }
            }
#pragma unroll
            for (int mi = 0; mi < 4; mi++)
#pragma unroll
                for (int nb = 0; nb < 4; nb++) {
                    mma16816(c[mi][2 * nb],     afr[cur][mi], bfr[cur][nb][0], bfr[cur][nb][1]);
                    mma16816(c[mi][2 * nb + 1], afr[cur][mi], bfr[cur][nb][2], bfr[cur][nb][3]);
                }
            cur = nxt;
        }
    }

    // Epilogue: direct f32 stores
    int rbase = m0 + wm * 64 + (lane >> 2);
    int cbase = n0 + wn * 64 + (lane & 3) * 2;
#pragma unroll
    for (int mi = 0; mi < 4; mi++) {
#pragma unroll
        for (int ni = 0; ni < 8; ni++) {
            float* p = out + (size_t)(rbase + mi * 16) * N_TOTAL + cbase + ni * 8;
            float2 v0 = make_float2(c[mi][ni][0], c[mi][ni][1]);
            float2 v1 = make_float2(c[mi][ni][2], c[mi][ni][3]);
            *reinterpret_cast<float2*>(p) = v0;
            *reinterpret_cast<float2*>(p + 8 * N_TOTAL) = v1;
        }
    }
}

// ---------------------------------------------------------------------------
extern "C" void kernel_launch(void* const* d_in, const int* in_sizes, int n_in,
                              void* d_out, int out_size) {
    const float* x      = (const float*)d_in[0];
    const int*   packed = (const int*)d_in[1];
    const float* d      = (const float*)d_in[2];
    const float* dmin   = (const float*)d_in[3];
    const int*   scales = (const int*)d_in[4];
    const int*   mins   = (const int*)d_in[5];
    float* out = (float*)d_out;

    (void)in_sizes; (void)n_in; (void)out_size;

    cudaFuncSetAttribute(k_gemm, cudaFuncAttributeMaxDynamicSharedMemorySize, SMEM_TOTAL);

    k_convert_x<<<(M_TOTAL * K_TOTAL / 8) / 256, 256>>>(x);
    k_dequant<<<(N_TOTAL * K_TOTAL / 2) / 256, 256>>>(packed, d, dmin, scales, mins);
    k_gemm<<<dim3(N_TOTAL / BN, M_TOTAL / BM), 256, SMEM_TOTAL>>>(out);
}